// round 13
// baseline (speedup 1.0000x reference)
#include <cuda_runtime.h>
#include <cstdint>

// Embedding gather: out[row, :] = weight[idx[row], :]
// idx: 16384 int32, weight: 50257 x 1024 fp32, out: 16384 x 1024 fp32.
// One CTA per 8 rows (2048 CTAs); each thread owns one float4 column:
// 8 independent LDG.128 then 8 streaming (.cs) STG.128.
//
// FINAL — measured 16.86-17.12us across 4 runs (R3/R7/R10/R12). Per replay
// the chip moves the compulsory 128 MiB in ~16.9us = ~7.9 TB/s aggregate,
// i.e. at the 8 TB/s HBM3e spec roofline. The .cs stores are load-bearing:
// writes buffer in L2 and drain overlapping the NEXT graph replay, so the
// replay period is read-bound. Falsified alternatives:
//   - TMA bulk-copy ring (R5): 25.3us — single-driver serialization.
//   - launch_bounds(256,4) MLP=8 (R4): 18.5us — MLP not binding.
//   - persistent grid (R6): 17.2us — wave quantization not a cost.
//   - LDG.256 + L2::evict_last pinning (R9): 25.3us — no replay reuse,
//     reg pressure killed load concurrency.
//   - st.global.wt (R11): 21.0us — writes forced into the kernel window,
//     destroying the write-drain/replay overlap.

static constexpr int EMSIZE       = 1024;
static constexpr int VEC_PER_ROW  = EMSIZE / 4;   // 256 float4 per row
static constexpr int VOCAB        = 50257;
static constexpr int ROWS_PER_CTA = 8;

__global__ __launch_bounds__(256) void embedding_gather_kernel(
    const int* __restrict__ idx,
    const float4* __restrict__ weight,
    float4* __restrict__ out,
    int n_rows)
{
    const int t    = threadIdx.x;                       // column (0..255)
    const int base = blockIdx.x * ROWS_PER_CTA;

    if (base + ROWS_PER_CTA <= n_rows) {
        // 8 indices as two vector loads (broadcast within CTA).
        const int4* ip = (const int4*)(idx + base);
        int4 i0 = __ldg(&ip[0]);
        int4 i1 = __ldg(&ip[1]);
        int r[ROWS_PER_CTA] = { i0.x, i0.y, i0.z, i0.w, i1.x, i1.y, i1.z, i1.w };
        #pragma unroll
        for (int i = 0; i < ROWS_PER_CTA; i++) {
            int v = r[i];
            r[i] = (v < 0) ? 0 : (v >= VOCAB ? VOCAB - 1 : v);
        }
        float4 w[ROWS_PER_CTA];
        #pragma unroll
        for (int i = 0; i < ROWS_PER_CTA; i++)
            w[i] = __ldg(&weight[(size_t)r[i] * VEC_PER_ROW + t]);
        #pragma unroll
        for (int i = 0; i < ROWS_PER_CTA; i++)
            __stcs(&out[(size_t)(base + i) * VEC_PER_ROW + t], w[i]);
    } else {
        // Tail (unused for 16384 rows, kept for safety).
        for (int i = 0; i < ROWS_PER_CTA; i++) {
            int row = base + i;
            if (row >= n_rows) break;
            int v = __ldg(&idx[row]);
            v = (v < 0) ? 0 : (v >= VOCAB ? VOCAB - 1 : v);
            float4 w = __ldg(&weight[(size_t)v * VEC_PER_ROW + t]);
            __stcs(&out[(size_t)row * VEC_PER_ROW + t], w);
        }
    }
}

extern "C" void kernel_launch(void* const* d_in, const int* in_sizes, int n_in,
                              void* d_out, int out_size) {
    const int*    idx    = (const int*)d_in[0];     // (2048, 8) int32 on device
    const float4* weight = (const float4*)d_in[1];  // (50257, 1024) fp32
    float4*       out    = (float4*)d_out;          // (2048, 8, 1024) fp32

    int n_rows = in_sizes[0];                       // 16384
    int n_ctas = (n_rows + ROWS_PER_CTA - 1) / ROWS_PER_CTA;  // 2048
    embedding_gather_kernel<<<n_ctas, 256>>>(idx, weight, out, n_rows);
}

// round 14
// speedup vs baseline: 1.0171x; 1.0171x over previous
#include <cuda_runtime.h>
#include <cstdint>

// Embedding gather: out[row, :] = weight[idx[row], :]
// idx: 16384 int32, weight: 50257 x 1024 fp32, out: 16384 x 1024 fp32.
// One CTA per 8 rows (2048 CTAs); each thread owns one float4 column:
// 8 independent LDG.128 then 8 streaming (.cs) STG.128.
//
// FINAL — measured 16.86-17.15us across 5 runs (R3/R7/R10/R12/R13); the
// spread is run-to-run variation. Per replay the chip moves the compulsory
// 128 MiB in ~16.9us = ~7.9 TB/s aggregate = the 8 TB/s HBM3e spec
// roofline. The .cs stores are load-bearing: writes buffer in L2 and drain
// overlapping the NEXT graph replay, so the replay period is read-bound.
// Falsified alternatives:
//   - TMA bulk-copy ring (R5): 25.3us — single-driver serialization.
//   - launch_bounds(256,4) MLP=8 (R4): 18.5us — MLP not binding.
//   - persistent grid (R6): 17.2us — wave quantization not a cost.
//   - LDG.256 + L2::evict_last pinning (R9): 25.3us — no replay reuse,
//     reg pressure killed load concurrency.
//   - st.global.wt (R11): 21.0us — writes forced into the kernel window,
//     destroying the write-drain/replay overlap.

static constexpr int EMSIZE       = 1024;
static constexpr int VEC_PER_ROW  = EMSIZE / 4;   // 256 float4 per row
static constexpr int VOCAB        = 50257;
static constexpr int ROWS_PER_CTA = 8;

__global__ __launch_bounds__(256) void embedding_gather_kernel(
    const int* __restrict__ idx,
    const float4* __restrict__ weight,
    float4* __restrict__ out,
    int n_rows)
{
    const int t    = threadIdx.x;                       // column (0..255)
    const int base = blockIdx.x * ROWS_PER_CTA;

    if (base + ROWS_PER_CTA <= n_rows) {
        // 8 indices as two vector loads (broadcast within CTA).
        const int4* ip = (const int4*)(idx + base);
        int4 i0 = __ldg(&ip[0]);
        int4 i1 = __ldg(&ip[1]);
        int r[ROWS_PER_CTA] = { i0.x, i0.y, i0.z, i0.w, i1.x, i1.y, i1.z, i1.w };
        #pragma unroll
        for (int i = 0; i < ROWS_PER_CTA; i++) {
            int v = r[i];
            r[i] = (v < 0) ? 0 : (v >= VOCAB ? VOCAB - 1 : v);
        }
        float4 w[ROWS_PER_CTA];
        #pragma unroll
        for (int i = 0; i < ROWS_PER_CTA; i++)
            w[i] = __ldg(&weight[(size_t)r[i] * VEC_PER_ROW + t]);
        #pragma unroll
        for (int i = 0; i < ROWS_PER_CTA; i++)
            __stcs(&out[(size_t)(base + i) * VEC_PER_ROW + t], w[i]);
    } else {
        // Tail (unused for 16384 rows, kept for safety).
        for (int i = 0; i < ROWS_PER_CTA; i++) {
            int row = base + i;
            if (row >= n_rows) break;
            int v = __ldg(&idx[row]);
            v = (v < 0) ? 0 : (v >= VOCAB ? VOCAB - 1 : v);
            float4 w = __ldg(&weight[(size_t)v * VEC_PER_ROW + t]);
            __stcs(&out[(size_t)row * VEC_PER_ROW + t], w);
        }
    }
}

extern "C" void kernel_launch(void* const* d_in, const int* in_sizes, int n_in,
                              void* d_out, int out_size) {
    const int*    idx    = (const int*)d_in[0];     // (2048, 8) int32 on device
    const float4* weight = (const float4*)d_in[1];  // (50257, 1024) fp32
    float4*       out    = (float4*)d_out;          // (2048, 8, 1024) fp32

    int n_rows = in_sizes[0];                       // 16384
    int n_ctas = (n_rows + ROWS_PER_CTA - 1) / ROWS_PER_CTA;  // 2048
    embedding_gather_kernel<<<n_ctas, 256>>>(idx, weight, out, n_rows);
}